// round 6
// baseline (speedup 1.0000x reference)
#include <cuda_runtime.h>

// Problem constants
#define BB 2
#define NN 2048
#define DIN 256
#define HH 8
#define DH 32
#define BH (BB*HH)            // 16
#define MSPLIT 8
#define MCHUNK (NN/MSPLIT)    // 256
#define TILE_M 64
#define NWORDS (NN/32)        // 64
#define SCALEF 0.17677669529663688f   // 1/sqrt(32)

typedef unsigned long long ull;

// ---------------- scratch (device globals; no allocations allowed) ----------
__device__ float    g_Q[BH*NN*DH];
__device__ float    g_K[BH*NN*DH];
__device__ float    g_V[BH*NN*DH];
__device__ unsigned g_bits[BB*NN*NWORDS];
__device__ float    g_pacc[MSPLIT*BH*NN*DH];
__device__ float    g_pl[MSPLIT*BH*NN];
__device__ float    g_attn[BB*NN*DIN];

// ---------------- f32x2 helpers (packed dual fp32 FMA, sm_100+) -------------
__device__ __forceinline__ ull pack2(float x, float y) {
    ull u; asm("mov.b64 %0, {%1, %2};" : "=l"(u) : "f"(x), "f"(y)); return u;
}
__device__ __forceinline__ float2 unpack2(ull u) {
    float2 v; asm("mov.b64 {%0, %1}, %2;" : "=f"(v.x), "=f"(v.y) : "l"(u)); return v;
}
__device__ __forceinline__ void ffma2(ull& d, ull a, ull b) {
    asm("fma.rn.f32x2 %0, %1, %2, %0;" : "+l"(d) : "l"(a), "l"(b));
}

// ---------------- kernel 0: adjacency -> bitmask ----------------------------
// one thread per 32 adjacency entries; grid covers exactly BB*NN*NWORDS words
__global__ __launch_bounds__(256) void adjbits_kernel(const float* __restrict__ adj) {
    int w = blockIdx.x * 256 + threadIdx.x;
    const float4* a = (const float4*)(adj + (size_t)w * 32);
    unsigned m = 0;
#pragma unroll
    for (int t = 0; t < 8; t++) {
        float4 v = a[t];
        m |= (v.x != 0.f ? 1u : 0u) << (4 * t + 0);
        m |= (v.y != 0.f ? 1u : 0u) << (4 * t + 1);
        m |= (v.z != 0.f ? 1u : 0u) << (4 * t + 2);
        m |= (v.w != 0.f ? 1u : 0u) << (4 * t + 3);
    }
    g_bits[w] = m;
}

// ---------------- GEMM: C[4096 x 64cols-per-block-col] = A(4096x256) @ W^T ---
// MODE 0: out[row*256+col] = acc + bias[col]          (output projection)
// MODE 1: scatter to [b,h,n,dh] layout, no bias       (Q/K/V projections)
template <int MODE>
__global__ __launch_bounds__(256) void gemm_kernel(const float* __restrict__ A,
                                                   const float* __restrict__ W,
                                                   const float* __restrict__ bias,
                                                   float* __restrict__ out) {
    __shared__ __align__(16) float As[16][68];
    __shared__ __align__(16) float Bs[16][68];
    const int tid = threadIdx.x;
    const int r0 = blockIdx.x * 64;
    const int c0 = blockIdx.y * 64;
    const int li = tid >> 2;
    const int lk = (tid & 3) * 4;
    const int i0 = (tid >> 4) * 4;
    const int j0 = (tid & 15) * 4;

    ull acc[4][2];
#pragma unroll
    for (int i = 0; i < 4; i++) { acc[i][0] = 0ull; acc[i][1] = 0ull; }

    for (int k0 = 0; k0 < 256; k0 += 16) {
        __syncthreads();
        float4 av = *(const float4*)(A + (size_t)(r0 + li) * 256 + k0 + lk);
        As[lk + 0][li] = av.x; As[lk + 1][li] = av.y;
        As[lk + 2][li] = av.z; As[lk + 3][li] = av.w;
        float4 wv = *(const float4*)(W + (size_t)(c0 + li) * 256 + k0 + lk);
        Bs[lk + 0][li] = wv.x; Bs[lk + 1][li] = wv.y;
        Bs[lk + 2][li] = wv.z; Bs[lk + 3][li] = wv.w;
        __syncthreads();
#pragma unroll
        for (int kk = 0; kk < 16; kk++) {
            float4 a = *(const float4*)&As[kk][i0];
            ulonglong2 bu = *(const ulonglong2*)&Bs[kk][j0];
            ull a0 = pack2(a.x, a.x), a1 = pack2(a.y, a.y);
            ull a2 = pack2(a.z, a.z), a3 = pack2(a.w, a.w);
            ffma2(acc[0][0], a0, bu.x); ffma2(acc[0][1], a0, bu.y);
            ffma2(acc[1][0], a1, bu.x); ffma2(acc[1][1], a1, bu.y);
            ffma2(acc[2][0], a2, bu.x); ffma2(acc[2][1], a2, bu.y);
            ffma2(acc[3][0], a3, bu.x); ffma2(acc[3][1], a3, bu.y);
        }
    }

#pragma unroll
    for (int ii = 0; ii < 4; ii++) {
        int row = r0 + i0 + ii;
#pragma unroll
        for (int jj = 0; jj < 2; jj++) {
            float2 v = unpack2(acc[ii][jj]);
            int c = c0 + j0 + jj * 2;
            if (MODE == 0) {
                out[(size_t)row * 256 + c]     = v.x + bias[c];
                out[(size_t)row * 256 + c + 1] = v.y + bias[c + 1];
            } else {
                int b_ = row >> 11, n = row & (NN - 1);
                int h = c >> 5, d = c & 31;
                size_t base = (((size_t)(b_ * HH + h)) * NN + n) * DH + d;
                out[base]     = v.x;
                out[base + 1] = v.y;
            }
        }
    }
}

// ---------------- attention: masked softmax(QK^T)V, m-split partials --------
// grid (NN/256, BH, MSPLIT), block 128; each thread owns 2 query rows.
// No running max needed: scores are bounded (|s| <= ~12), exp()/sum is exact
// softmax in fp32 range.
__global__ __launch_bounds__(128) void attn_kernel() {
    __shared__ __align__(16) float Ks[TILE_M * DH];
    __shared__ __align__(16) float Vs[TILE_M * DH];
    const int tid = threadIdx.x;
    const int bh = blockIdx.y;
    const int b = bh >> 3;
    const int n0 = blockIdx.x * 256 + tid * 2;
    const int msBase = blockIdx.z * MCHUNK;

    ull q0[16], q1[16], acc0[16], acc1[16];
    {
        const ulonglong2* p0 = (const ulonglong2*)(g_Q + ((size_t)bh * NN + n0) * DH);
        const ulonglong2* p1 = (const ulonglong2*)(g_Q + ((size_t)bh * NN + n0 + 1) * DH);
#pragma unroll
        for (int i = 0; i < 8; i++) {
            ulonglong2 t0 = p0[i]; q0[2 * i] = t0.x; q0[2 * i + 1] = t0.y;
            ulonglong2 t1 = p1[i]; q1[2 * i] = t1.x; q1[2 * i + 1] = t1.y;
        }
    }
#pragma unroll
    for (int i = 0; i < 16; i++) { acc0[i] = 0ull; acc1[i] = 0ull; }
    float l0 = 0.f, l1 = 0.f;

    const unsigned* bits0 = g_bits + ((size_t)b * NN + n0) * NWORDS;
    const unsigned* bits1 = bits0 + NWORDS;

    for (int t = 0; t < MCHUNK; t += TILE_M) {
        const int m0 = msBase + t;
        __syncthreads();
        {
            const float4* Kg = (const float4*)(g_K + ((size_t)bh * NN + m0) * DH);
            const float4* Vg = (const float4*)(g_V + ((size_t)bh * NN + m0) * DH);
            float4* Ks4 = (float4*)Ks;
            float4* Vs4 = (float4*)Vs;
#pragma unroll
            for (int i = 0; i < 4; i++) {
                Ks4[tid + 128 * i] = Kg[tid + 128 * i];
                Vs4[tid + 128 * i] = Vg[tid + 128 * i];
            }
        }
        __syncthreads();
        const int w = m0 >> 5;
#pragma unroll
        for (int half = 0; half < 2; half++) {
            const unsigned wa = bits0[w + half];
            const unsigned wb = bits1[w + half];
#pragma unroll 4
            for (int jj = 0; jj < 32; jj++) {
                const int j = half * 32 + jj;
                const ulonglong2* kr = (const ulonglong2*)(Ks + j * DH);
                ull d00 = 0, d01 = 0, d02 = 0, d03 = 0;
                ull d10 = 0, d11 = 0, d12 = 0, d13 = 0;
#pragma unroll
                for (int k = 0; k < 4; k++) {
                    ulonglong2 ka = kr[2 * k], kb = kr[2 * k + 1];
                    ffma2(d00, q0[4 * k + 0], ka.x); ffma2(d01, q0[4 * k + 1], ka.y);
                    ffma2(d02, q0[4 * k + 2], kb.x); ffma2(d03, q0[4 * k + 3], kb.y);
                    ffma2(d10, q1[4 * k + 0], ka.x); ffma2(d11, q1[4 * k + 1], ka.y);
                    ffma2(d12, q1[4 * k + 2], kb.x); ffma2(d13, q1[4 * k + 3], kb.y);
                }
                float2 e0 = unpack2(d00), e1 = unpack2(d01), e2 = unpack2(d02), e3 = unpack2(d03);
                float s0 = ((e0.x + e0.y) + (e1.x + e1.y)) + ((e2.x + e2.y) + (e3.x + e3.y));
                float2 f0 = unpack2(d10), f1 = unpack2(d11), f2 = unpack2(d12), f3 = unpack2(d13);
                float s1 = ((f0.x + f0.y) + (f1.x + f1.y)) + ((f2.x + f2.y) + (f3.x + f3.y));
                float p0 = ((wa >> jj) & 1u) ? __expf(s0 * SCALEF) : 0.f;
                float p1 = ((wb >> jj) & 1u) ? __expf(s1 * SCALEF) : 0.f;
                l0 += p0; l1 += p1;
                const ull pu0 = pack2(p0, p0);
                const ull pu1 = pack2(p1, p1);
                const ulonglong2* vr = (const ulonglong2*)(Vs + j * DH);
#pragma unroll
                for (int k = 0; k < 8; k++) {
                    ulonglong2 vv = vr[k];
                    ffma2(acc0[2 * k], pu0, vv.x); ffma2(acc0[2 * k + 1], pu0, vv.y);
                    ffma2(acc1[2 * k], pu1, vv.x); ffma2(acc1[2 * k + 1], pu1, vv.y);
                }
            }
        }
    }

    // write m-split partials
    {
        size_t base = (((size_t)blockIdx.z * BH + bh) * NN + n0) * DH;
        ulonglong2* pa = (ulonglong2*)(g_pacc + base);
        ulonglong2* pb = (ulonglong2*)(g_pacc + base + DH);
#pragma unroll
        for (int i = 0; i < 8; i++) {
            pa[i] = make_ulonglong2(acc0[2 * i], acc0[2 * i + 1]);
            pb[i] = make_ulonglong2(acc1[2 * i], acc1[2 * i + 1]);
        }
        size_t lbase = ((size_t)blockIdx.z * BH + bh) * NN + n0;
        g_pl[lbase]     = l0;
        g_pl[lbase + 1] = l1;
    }
}

// ---------------- combine m-split partials -> concat-head layout ------------
__global__ __launch_bounds__(256) void combine_kernel() {
    int idx = blockIdx.x * 256 + threadIdx.x;   // over BH*NN*DH = 2^20, exact grid
    int d = idx & 31;
    int n = (idx >> 5) & (NN - 1);
    int bh = idx >> 16;
    float a = 0.f, l = 0.f;
#pragma unroll
    for (int ms = 0; ms < MSPLIT; ms++) {
        a += g_pacc[(((size_t)ms * BH + bh) * NN + n) * DH + d];
        l += g_pl[((size_t)ms * BH + bh) * NN + n];
    }
    int b_ = bh >> 3, h = bh & 7;
    g_attn[((size_t)(b_ * NN + n)) * DIN + h * DH + d] = a / l;
}

// ---------------- launcher ---------------------------------------------------
extern "C" void kernel_launch(void* const* d_in, const int* in_sizes, int n_in,
                              void* d_out, int out_size) {
    const float* x   = (const float*)d_in[0];
    const float* adj = (const float*)d_in[1];
    const float* Wq  = (const float*)d_in[2];
    const float* Wk  = (const float*)d_in[3];
    const float* Wv  = (const float*)d_in[4];
    const float* Wo  = (const float*)d_in[5];
    const float* bo  = (const float*)d_in[6];
    float* out = (float*)d_out;
    (void)in_sizes; (void)n_in; (void)out_size;

    void *pQ, *pK, *pV, *pAttn;
    cudaGetSymbolAddress(&pQ, g_Q);
    cudaGetSymbolAddress(&pK, g_K);
    cudaGetSymbolAddress(&pV, g_V);
    cudaGetSymbolAddress(&pAttn, g_attn);

    adjbits_kernel<<<BB * NN * NWORDS / 256, 256>>>(adj);
    gemm_kernel<1><<<dim3(64, 4), 256>>>(x, Wq, nullptr, (float*)pQ);
    gemm_kernel<1><<<dim3(64, 4), 256>>>(x, Wk, nullptr, (float*)pK);
    gemm_kernel<1><<<dim3(64, 4), 256>>>(x, Wv, nullptr, (float*)pV);
    attn_kernel<<<dim3(NN / 256, BH, MSPLIT), 128>>>();
    combine_kernel<<<BH * NN * DH / 256, 256>>>();
    gemm_kernel<0><<<dim3(64, 4), 256>>>((const float*)pAttn, Wo, bo, out);
}

// round 10
// speedup vs baseline: 1.8182x; 1.8182x over previous
#include <cuda_runtime.h>
#include <cuda_bf16.h>
#include <cstdint>

#define BB 2
#define NN 2048
#define DIN 256
#define HH 8
#define DH 32
#define BH (BB*HH)            // 16
#define NWORDS (NN/32)        // 64
#define SCALEF 0.17677669529663688f   // 1/sqrt(32)
#define NTILES (NN/64)        // 32

typedef unsigned long long ull;
typedef uint32_t u32;

// ---------------- scratch ----------------------------------------------------
__device__ unsigned      g_bits[BB*NN*NWORDS];
__device__ __nv_bfloat16 g_Qb[BH*NN*64];   // [bh][n][hi32|lo32], prescaled by 1/sqrt(dh)
__device__ __nv_bfloat16 g_Kb[BH*NN*64];   // [bh][n][hi32|lo32]
__device__ __nv_bfloat16 g_Vtb[BH*64*NN];  // [bh][row: d<32 Vh^T | d>=32 Vl^T][n]
__device__ float         g_attn[BB*NN*DIN];

// ---------------- f32x2 helpers ----------------------------------------------
__device__ __forceinline__ ull pack2(float x, float y) {
    ull u; asm("mov.b64 %0, {%1, %2};" : "=l"(u) : "f"(x), "f"(y)); return u;
}
__device__ __forceinline__ float2 unpack2(ull u) {
    float2 v; asm("mov.b64 {%0, %1}, %2;" : "=f"(v.x), "=f"(v.y) : "l"(u)); return v;
}
__device__ __forceinline__ void ffma2(ull& d, ull a, ull b) {
    asm("fma.rn.f32x2 %0, %1, %2, %0;" : "+l"(d) : "l"(a), "l"(b));
}

#define SWZ(o) ((o) ^ (((o) >> 3) & 0x70))

// mma.sync m16n8k16 bf16 -> f32 accumulate (portable, sm_80+ PTX)
#define MMA16816(d, a, B0, B1) asm volatile( \
    "mma.sync.aligned.m16n8k16.row.col.f32.bf16.bf16.f32 " \
    "{%0,%1,%2,%3},{%4,%5,%6,%7},{%8,%9},{%0,%1,%2,%3};" \
    : "+f"((d)[0]), "+f"((d)[1]), "+f"((d)[2]), "+f"((d)[3]) \
    : "r"((a)[0]), "r"((a)[1]), "r"((a)[2]), "r"((a)[3]), "r"(B0), "r"(B1))

__device__ __forceinline__ u32 bf16x2_of(float hi, float lo) {
    u32 r; asm("cvt.rn.bf16x2.f32 %0, %1, %2;" : "=r"(r) : "f"(hi), "f"(lo));
    return r;   // upper half = hi arg, lower half = lo arg
}

// ---------------- adjacency -> bitmask ---------------------------------------
__global__ __launch_bounds__(256) void adjbits_kernel(const float* __restrict__ adj) {
    int w = blockIdx.x * 256 + threadIdx.x;
    const float4* a = (const float4*)(adj + (size_t)w * 32);
    unsigned m = 0;
#pragma unroll
    for (int t = 0; t < 8; t++) {
        float4 v = a[t];
        m |= (v.x != 0.f ? 1u : 0u) << (4 * t + 0);
        m |= (v.y != 0.f ? 1u : 0u) << (4 * t + 1);
        m |= (v.z != 0.f ? 1u : 0u) << (4 * t + 2);
        m |= (v.w != 0.f ? 1u : 0u) << (4 * t + 3);
    }
    g_bits[w] = m;
}

// ---------------- fused QKV GEMM: z=0 Q(split,scaled) z=1 K(split) z=2 V(T+split)
__global__ __launch_bounds__(256) void gemm_qkv(const float* __restrict__ A,
                                                const float* __restrict__ Wq,
                                                const float* __restrict__ Wk,
                                                const float* __restrict__ Wv) {
    __shared__ __align__(16) float As[16][68];
    __shared__ __align__(16) float Bs[16][68];
    const int z = blockIdx.z;
    const float* W = (z == 0) ? Wq : (z == 1 ? Wk : Wv);
    const float scale = (z == 0) ? SCALEF : 1.0f;
    const int tid = threadIdx.x;
    const int r0 = blockIdx.x * 64;
    const int c0 = blockIdx.y * 64;
    const int li = tid >> 2;
    const int lk = (tid & 3) * 4;
    const int i0 = (tid >> 4) * 4;
    const int j0 = (tid & 15) * 4;

    ull acc[4][2];
#pragma unroll
    for (int i = 0; i < 4; i++) { acc[i][0] = 0ull; acc[i][1] = 0ull; }

    for (int k0 = 0; k0 < 256; k0 += 16) {
        __syncthreads();
        float4 av = *(const float4*)(A + (size_t)(r0 + li) * 256 + k0 + lk);
        As[lk + 0][li] = av.x; As[lk + 1][li] = av.y;
        As[lk + 2][li] = av.z; As[lk + 3][li] = av.w;
        float4 wv = *(const float4*)(W + (size_t)(c0 + li) * 256 + k0 + lk);
        Bs[lk + 0][li] = wv.x; Bs[lk + 1][li] = wv.y;
        Bs[lk + 2][li] = wv.z; Bs[lk + 3][li] = wv.w;
        __syncthreads();
#pragma unroll
        for (int kk = 0; kk < 16; kk++) {
            float4 a = *(const float4*)&As[kk][i0];
            ulonglong2 bu = *(const ulonglong2*)&Bs[kk][j0];
            ull a0 = pack2(a.x, a.x), a1 = pack2(a.y, a.y);
            ull a2 = pack2(a.z, a.z), a3 = pack2(a.w, a.w);
            ffma2(acc[0][0], a0, bu.x); ffma2(acc[0][1], a0, bu.y);
            ffma2(acc[1][0], a1, bu.x); ffma2(acc[1][1], a1, bu.y);
            ffma2(acc[2][0], a2, bu.x); ffma2(acc[2][1], a2, bu.y);
            ffma2(acc[3][0], a3, bu.x); ffma2(acc[3][1], a3, bu.y);
        }
    }

#pragma unroll
    for (int ii = 0; ii < 4; ii++) {
        int row = r0 + i0 + ii;
        int b_ = row >> 11, n = row & (NN - 1);
#pragma unroll
        for (int jj = 0; jj < 2; jj++) {
            float2 v = unpack2(acc[ii][jj]);
#pragma unroll
            for (int s = 0; s < 2; s++) {
                int c = c0 + j0 + jj * 2 + s;
                float val = (s ? v.y : v.x) * scale;
                int h = c >> 5, d = c & 31, bh = b_ * HH + h;
                __nv_bfloat16 hb = __float2bfloat16(val);
                __nv_bfloat16 lb = __float2bfloat16(val - __bfloat162float(hb));
                if (z < 2) {
                    __nv_bfloat16* dst = (z == 0 ? g_Qb : g_Kb) + ((size_t)bh * NN + n) * 64;
                    dst[d] = hb; dst[32 + d] = lb;
                } else {
                    g_Vtb[((size_t)bh * 64 + d) * NN + n] = hb;
                    g_Vtb[((size_t)bh * 64 + 32 + d) * NN + n] = lb;
                }
            }
        }
    }
}

// ---------------- output projection GEMM (+bias) -----------------------------
__global__ __launch_bounds__(256) void gemm_out(const float* __restrict__ A,
                                                const float* __restrict__ W,
                                                const float* __restrict__ bias,
                                                float* __restrict__ out) {
    __shared__ __align__(16) float As[16][68];
    __shared__ __align__(16) float Bs[16][68];
    const int tid = threadIdx.x;
    const int r0 = blockIdx.x * 64;
    const int c0 = blockIdx.y * 64;
    const int li = tid >> 2;
    const int lk = (tid & 3) * 4;
    const int i0 = (tid >> 4) * 4;
    const int j0 = (tid & 15) * 4;

    ull acc[4][2];
#pragma unroll
    for (int i = 0; i < 4; i++) { acc[i][0] = 0ull; acc[i][1] = 0ull; }

    for (int k0 = 0; k0 < 256; k0 += 16) {
        __syncthreads();
        float4 av = *(const float4*)(A + (size_t)(r0 + li) * 256 + k0 + lk);
        As[lk + 0][li] = av.x; As[lk + 1][li] = av.y;
        As[lk + 2][li] = av.z; As[lk + 3][li] = av.w;
        float4 wv = *(const float4*)(W + (size_t)(c0 + li) * 256 + k0 + lk);
        Bs[lk + 0][li] = wv.x; Bs[lk + 1][li] = wv.y;
        Bs[lk + 2][li] = wv.z; Bs[lk + 3][li] = wv.w;
        __syncthreads();
#pragma unroll
        for (int kk = 0; kk < 16; kk++) {
            float4 a = *(const float4*)&As[kk][i0];
            ulonglong2 bu = *(const ulonglong2*)&Bs[kk][j0];
            ull a0 = pack2(a.x, a.x), a1 = pack2(a.y, a.y);
            ull a2 = pack2(a.z, a.z), a3 = pack2(a.w, a.w);
            ffma2(acc[0][0], a0, bu.x); ffma2(acc[0][1], a0, bu.y);
            ffma2(acc[1][0], a1, bu.x); ffma2(acc[1][1], a1, bu.y);
            ffma2(acc[2][0], a2, bu.x); ffma2(acc[2][1], a2, bu.y);
            ffma2(acc[3][0], a3, bu.x); ffma2(acc[3][1], a3, bu.y);
        }
    }
#pragma unroll
    for (int ii = 0; ii < 4; ii++) {
        int row = r0 + i0 + ii;
#pragma unroll
        for (int jj = 0; jj < 2; jj++) {
            float2 v = unpack2(acc[ii][jj]);
            int c = c0 + j0 + jj * 2;
            out[(size_t)row * 256 + c]     = v.x + bias[c];
            out[(size_t)row * 256 + c + 1] = v.y + bias[c + 1];
        }
    }
}

// ---------------- HMMA flash attention ---------------------------------------
// grid (16 q-tiles, 16 bh), 128 threads = 4 warps. Warp w owns q rows [32w,32w+32).
// smem: K tile 8KB (64 keys x 64 bf16, SWZ), V tile 8KB (64 d-rows: hi|lo x 64 keys,
//       SWZ), mask bits 1KB (128 rows x 64 bits).
#define SM_KB 0
#define SM_VB 8192
#define SM_MB 16384
#define SM_TOT 17408

__global__ __launch_bounds__(128) void attn_kernel() {
    __shared__ __align__(16) char sm[SM_TOT];
    const int tid = threadIdx.x;
    const int wid = tid >> 5, lane = tid & 31;
    const int g = lane >> 2, tig = lane & 3;     // groupID, threadInGroup
    const int bh = blockIdx.y, b = bh >> 3;
    const int n0 = blockIdx.x * 128;

    // ---- Q A-fragments in registers for the whole kernel ----
    u32 aQ[2][4][4];
    {
        const char* qg = (const char*)g_Qb + ((size_t)(bh * NN + n0 + wid * 32)) * 128;
#pragma unroll
        for (int mi = 0; mi < 2; mi++)
#pragma unroll
            for (int ks = 0; ks < 4; ks++)
#pragma unroll
                for (int r = 0; r < 4; r++) {
                    int row = 16 * mi + g + 8 * (r & 1);
                    int kb = 4 * tig + 32 * ks + ((r >= 2) ? 16 : 0);
                    aQ[mi][ks][r] = *(const u32*)(qg + row * 128 + kb);
                }
    }

    float o[2][4][4];
#pragma unroll
    for (int mi = 0; mi < 2; mi++)
#pragma unroll
        for (int tn = 0; tn < 4; tn++)
#pragma unroll
            for (int c = 0; c < 4; c++) o[mi][tn][c] = 0.f;
    float lsum[2][2] = {{0.f, 0.f}, {0.f, 0.f}};

    for (int t = 0; t < NTILES; t++) {
        __syncthreads();
        // ---- stage K tile: 64 rows x 128B contiguous ----
        {
            const char* kg = (const char*)g_Kb + ((size_t)(bh * NN + t * 64)) * 128;
#pragma unroll
            for (int i = 0; i < 4; i++) {
                int off = (tid + 128 * i) * 16;
                *(uint4*)(sm + SM_KB + SWZ(off)) = *(const uint4*)(kg + off);
            }
        }
        // ---- stage V^T tile: 64 rows (d: 0-31 hi, 32-63 lo) x 128B,
        //      global row stride NN*2 bytes ----
        {
            const char* vg = (const char*)g_Vtb + (size_t)bh * 64 * (NN * 2) + t * 128;
#pragma unroll
            for (int i = 0; i < 4; i++) {
                int cc = tid + 128 * i;
                int d = cc >> 3, u = cc & 7;
                *(uint4*)(sm + SM_VB + SWZ(cc * 16)) =
                    *(const uint4*)(vg + (size_t)d * (NN * 2) + u * 16);
            }
        }
        // ---- stage mask bits: 64 bits per q row ----
        *(uint2*)(sm + SM_MB + tid * 8) =
            *(const uint2*)(g_bits + ((size_t)(b * NN + n0 + tid)) * NWORDS + t * 2);
        __syncthreads();

        // ---- S = Qh.Kh + Ql.Kh + Qh.Kl  (m32 x n64, per warp) ----
        float cf[2][8][4];
#pragma unroll
        for (int mi = 0; mi < 2; mi++)
#pragma unroll
            for (int tt = 0; tt < 8; tt++)
#pragma unroll
                for (int c = 0; c < 4; c++) cf[mi][tt][c] = 0.f;

#pragma unroll
        for (int ks = 0; ks < 4; ks++) {
            u32 b0[8], b1[8];
#pragma unroll
            for (int tt = 0; tt < 8; tt++) {
                int j = 8 * tt + g;
                int kb = 4 * tig + 32 * ks;
                b0[tt] = *(const u32*)(sm + SM_KB + SWZ(j * 128 + kb));
                b1[tt] = *(const u32*)(sm + SM_KB + SWZ(j * 128 + kb + 16));
            }
            // B k-step ks pairs with A k-steps: ks<2 -> {ks (hi.hi), ks+2 (lo.hi)};
            // ks>=2 -> {ks-2 (hi.lo)}
#pragma unroll
            for (int tt = 0; tt < 8; tt++)
#pragma unroll
                for (int mi = 0; mi < 2; mi++) {
                    if (ks < 2) {
                        MMA16816(cf[mi][tt], aQ[mi][ks], b0[tt], b1[tt]);
                        MMA16816(cf[mi][tt], aQ[mi][ks + 2], b0[tt], b1[tt]);
                    } else {
                        MMA16816(cf[mi][tt], aQ[mi][ks - 2], b0[tt], b1[tt]);
                    }
                }
        }

        // ---- mask + exp (exact softmax numerators; scores bounded) ----
#pragma unroll
        for (int mi = 0; mi < 2; mi++) {
            ull mA = *(const ull*)(sm + SM_MB + (wid * 32 + 16 * mi + g) * 8);
            ull mB = *(const ull*)(sm + SM_MB + (wid * 32 + 16 * mi + g + 8) * 8);
#pragma unroll
            for (int tt = 0; tt < 8; tt++) {
                int j0 = 8 * tt + 2 * tig;
                float p0 = ((mA >> j0) & 1ull)       ? __expf(cf[mi][tt][0]) : 0.f;
                float p1 = ((mA >> (j0 + 1)) & 1ull) ? __expf(cf[mi][tt][1]) : 0.f;
                float p2 = ((mB >> j0) & 1ull)       ? __expf(cf[mi][tt][2]) : 0.f;
                float p3 = ((mB >> (j0 + 1)) & 1ull) ? __expf(cf[mi][tt][3]) : 0.f;
                lsum[mi][0] += p0 + p1;
                lsum[mi][1] += p2 + p3;
                cf[mi][tt][0] = p0; cf[mi][tt][1] = p1;
                cf[mi][tt][2] = p2; cf[mi][tt][3] = p3;
            }
        }

        // ---- O += Ph.Vh + Ph.Vl + Pl.Vh  (C-fragment -> A-fragment identity) ----
#pragma unroll
        for (int s = 0; s < 4; s++) {
            u32 vh0[4], vh1[4], vl0[4], vl1[4];
#pragma unroll
            for (int tn = 0; tn < 4; tn++) {
                int d = 8 * tn + g;
                int jb = 4 * tig + 32 * s;
                vh0[tn] = *(const u32*)(sm + SM_VB + SWZ(d * 128 + jb));
                vh1[tn] = *(const u32*)(sm + SM_VB + SWZ(d * 128 + jb + 16));
                vl0[tn] = *(const u32*)(sm + SM_VB + SWZ((d + 32) * 128 + jb));
                vl1[tn] = *(const u32*)(sm + SM_VB + SWZ((d + 32) * 128 + jb + 16));
            }
#pragma unroll
            for (int mi = 0; mi < 2; mi++) {
                u32 Ah[4], Al[4];
#pragma unroll
                for (int half = 0; half < 2; half++) {       // C tiles 2s, 2s+1
                    const float* c4 = cf[mi][2 * s + half];
                    u32 h01 = bf16x2_of(c4[1], c4[0]);
                    u32 h23 = bf16x2_of(c4[3], c4[2]);
                    Ah[2 * half]     = h01;
                    Ah[2 * half + 1] = h23;
                    float r0 = __uint_as_float(h01 << 16);
                    float r1 = __uint_as_float(h01 & 0xffff0000u);
                    float r2 = __uint_as_float(h23 << 16);
                    float r3 = __uint_as_float(h23 & 0xffff0000u);
                    Al[2 * half]     = bf16x2_of(c4[1] - r1, c4[0] - r0);
                    Al[2 * half + 1] = bf16x2_of(c4[3] - r3, c4[2] - r2);
                }
#pragma unroll
                for (int tn = 0; tn < 4; tn++) {
                    MMA16816(o[mi][tn], Ah, vh0[tn], vh1[tn]);
                    MMA16816(o[mi][tn], Ah, vl0[tn], vl1[tn]);
                    MMA16816(o[mi][tn], Al, vh0[tn], vh1[tn]);
                }
            }
        }
    }

    // ---- reduce l across the quad (lanes sharing the same rows) ----
#pragma unroll
    for (int mi = 0; mi < 2; mi++)
#pragma unroll
        for (int r = 0; r < 2; r++) {
            float v = lsum[mi][r];
            v += __shfl_xor_sync(0xffffffffu, v, 1);
            v += __shfl_xor_sync(0xffffffffu, v, 2);
            lsum[mi][r] = v;
        }

    // ---- normalize + write concat-head layout ----
    const int hcol = (bh & 7) * 32;
#pragma unroll
    for (int mi = 0; mi < 2; mi++) {
        int rA = n0 + wid * 32 + 16 * mi + g;
        float invA = 1.f / lsum[mi][0];
        float invB = 1.f / lsum[mi][1];
        float* baseA = g_attn + ((size_t)b * NN + rA) * 256 + hcol;
        float* baseB = baseA + 8 * 256;
#pragma unroll
        for (int tn = 0; tn < 4; tn++) {
            int dl = 8 * tn + 2 * tig;
            *(float2*)(baseA + dl) = make_float2(o[mi][tn][0] * invA, o[mi][tn][1] * invA);
            *(float2*)(baseB + dl) = make_float2(o[mi][tn][2] * invB, o[mi][tn][3] * invB);
        }
    }
}

// ---------------- launcher ---------------------------------------------------
extern "C" void kernel_launch(void* const* d_in, const int* in_sizes, int n_in,
                              void* d_out, int out_size) {
    const float* x   = (const float*)d_in[0];
    const float* adj = (const float*)d_in[1];
    const float* Wq  = (const float*)d_in[2];
    const float* Wk  = (const float*)d_in[3];
    const float* Wv  = (const float*)d_in[4];
    const float* Wo  = (const float*)d_in[5];
    const float* bo  = (const float*)d_in[6];
    float* out = (float*)d_out;
    (void)in_sizes; (void)n_in; (void)out_size;

    void* pAttn;
    cudaGetSymbolAddress(&pAttn, g_attn);

    adjbits_kernel<<<BB * NN * NWORDS / 256, 256>>>(adj);
    gemm_qkv<<<dim3(64, 4, 3), 256>>>(x, Wq, Wk, Wv);
    attn_kernel<<<dim3(NN / 128, BH), 128>>>();
    gemm_out<<<dim3(64, 4), 256>>>((const float*)pAttn, Wo, bo, out);
}

// round 11
// speedup vs baseline: 2.3354x; 1.2844x over previous
#include <cuda_runtime.h>
#include <cuda_bf16.h>
#include <cstdint>

#define BB 2
#define NN 2048
#define DIN 256
#define HH 8
#define DH 32
#define BH (BB*HH)            // 16
#define NWORDS (NN/32)        // 64
#define SCALEF 0.17677669529663688f   // 1/sqrt(32)
#define NTILES (NN/64)        // 32

typedef unsigned long long ull;
typedef uint32_t u32;

// ---------------- scratch ----------------------------------------------------
__device__ unsigned      g_bits[BB*NN*NWORDS];
__device__ __nv_bfloat16 g_Qb[BH*NN*64];    // [bh][n][hi32|lo32], prescaled
__device__ __nv_bfloat16 g_Kb[BH*NN*64];    // [bh][n][hi32|lo32]
__device__ __nv_bfloat16 g_Vtb[BH*64*NN];   // [bh][d<32 Vh^T | d>=32 Vl^T][n]
__device__ __nv_bfloat16 g_xb[4096*512];    // [row][hi256|lo256]
__device__ __nv_bfloat16 g_Wb[4*256*512];   // [w][n][hi256|lo256]  w: q,k,v,o
__device__ __nv_bfloat16 g_attnb[4096*512]; // [row][hi256|lo256]

#define SWZ(o) ((o) ^ (((o) >> 3) & 0x70))

// mma.sync m16n8k16 bf16 -> f32 accumulate (portable, sm_80+ PTX)
#define MMA16816(d, a, B0, B1) asm volatile( \
    "mma.sync.aligned.m16n8k16.row.col.f32.bf16.bf16.f32 " \
    "{%0,%1,%2,%3},{%4,%5,%6,%7},{%8,%9},{%0,%1,%2,%3};" \
    : "+f"((d)[0]), "+f"((d)[1]), "+f"((d)[2]), "+f"((d)[3]) \
    : "r"((a)[0]), "r"((a)[1]), "r"((a)[2]), "r"((a)[3]), "r"(B0), "r"(B1))

__device__ __forceinline__ u32 bf16x2_of(float hi, float lo) {
    u32 r; asm("cvt.rn.bf16x2.f32 %0, %1, %2;" : "=r"(r) : "f"(hi), "f"(lo));
    return r;   // upper half = hi arg, lower half = lo arg
}

// ---------------- adjacency -> bitmask ---------------------------------------
__global__ __launch_bounds__(256) void adjbits_kernel(const float* __restrict__ adj) {
    int w = blockIdx.x * 256 + threadIdx.x;
    const float4* a = (const float4*)(adj + (size_t)w * 32);
    unsigned m = 0;
#pragma unroll
    for (int t = 0; t < 8; t++) {
        float4 v = a[t];
        m |= (v.x != 0.f ? 1u : 0u) << (4 * t + 0);
        m |= (v.y != 0.f ? 1u : 0u) << (4 * t + 1);
        m |= (v.z != 0.f ? 1u : 0u) << (4 * t + 2);
        m |= (v.w != 0.f ? 1u : 0u) << (4 * t + 3);
    }
    g_bits[w] = m;
}

// ---------------- split fp32 -> bf16 hi/lo ------------------------------------
__device__ __forceinline__ void split4(float4 v, u32& hA, u32& hB, u32& lA, u32& lB) {
    hA = bf16x2_of(v.y, v.x);
    hB = bf16x2_of(v.w, v.z);
    float r0 = __uint_as_float(hA << 16), r1 = __uint_as_float(hA & 0xffff0000u);
    float r2 = __uint_as_float(hB << 16), r3 = __uint_as_float(hB & 0xffff0000u);
    lA = bf16x2_of(v.y - r1, v.x - r0);
    lB = bf16x2_of(v.w - r3, v.z - r2);
}

__global__ __launch_bounds__(256) void split_x(const float* __restrict__ src) {
    int idx = blockIdx.x * 256 + threadIdx.x;      // quads over 4096*64
    float4 v = ((const float4*)src)[idx];
    int row = idx >> 6, c4 = (idx & 63) * 4;
    u32 hA, hB, lA, lB; split4(v, hA, hB, lA, lB);
    *(uint2*)(g_xb + (size_t)row * 512 + c4)       = make_uint2(hA, hB);
    *(uint2*)(g_xb + (size_t)row * 512 + 256 + c4) = make_uint2(lA, lB);
}

__global__ __launch_bounds__(256) void split_w(const float* __restrict__ Wq,
                                               const float* __restrict__ Wk,
                                               const float* __restrict__ Wv,
                                               const float* __restrict__ Wo) {
    int idx = blockIdx.x * 256 + threadIdx.x;      // quads over 4*256*64
    int w = idx >> 14;
    const float* src = (w == 0) ? Wq : (w == 1) ? Wk : (w == 2) ? Wv : Wo;
    int li = idx & 16383;
    float4 v = ((const float4*)src)[li];
    int row = li >> 6, c4 = (li & 63) * 4;
    u32 hA, hB, lA, lB; split4(v, hA, hB, lA, lB);
    __nv_bfloat16* d = g_Wb + ((size_t)w * 256 + row) * 512;
    *(uint2*)(d + c4)       = make_uint2(hA, hB);
    *(uint2*)(d + 256 + c4) = make_uint2(lA, lB);
}

// ---------------- HMMA GEMM: C(4096x256) = A(4096x256) @ W^T -----------------
// A, W stored split bf16 (hi|lo, 512 wide). Effective K=768:
//   pass 0: Ah.Wh  pass 1: Al.Wh  pass 2: Ah.Wl   (drop Al.Wl ~ 2^-16)
// Block tile 128m x 64n, 4 warps (warp = 32 m-rows). MODE 0: +bias -> fp32 out.
// MODE 1: z=blockIdx.z picks {Q,K,V}; scatter split-bf16 to g_Qb/g_Kb/g_Vtb.
#define GS_A 0
#define GS_B 16384
#define GS_TOT 24576

template <int MODE>
__global__ __launch_bounds__(128) void hgemm(const __nv_bfloat16* __restrict__ A,
                                             const float* __restrict__ bias,
                                             float* __restrict__ out) {
    __shared__ __align__(16) char sm[GS_TOT];
    const int tid = threadIdx.x;
    const int wid = tid >> 5, lane = tid & 31;
    const int g = lane >> 2, tig = lane & 3;
    const int m0 = blockIdx.x * 128;
    const int n0 = blockIdx.y * 64;
    const int z = (MODE == 1) ? blockIdx.z : 3;
    const __nv_bfloat16* W = g_Wb + (size_t)z * 256 * 512;
    const float scale = (MODE == 1 && z == 0) ? SCALEF : 1.0f;

    float o[2][8][4];
#pragma unroll
    for (int mi = 0; mi < 2; mi++)
#pragma unroll
        for (int tt = 0; tt < 8; tt++)
#pragma unroll
            for (int c = 0; c < 4; c++) o[mi][tt][c] = 0.f;

#pragma unroll 1
    for (int c = 0; c < 12; c++) {
        const int p = c >> 2, k0 = (c & 3) * 64;
        const int aCol = ((p == 1) ? 256 : 0) + k0;
        const int bCol = ((p == 2) ? 256 : 0) + k0;
        __syncthreads();
        {
            const char* ag = (const char*)(A + (size_t)m0 * 512 + aCol);
#pragma unroll
            for (int i = 0; i < 8; i++) {
                int off = (tid + 128 * i) * 16;
                int row = off >> 7, wi = off & 127;
                *(uint4*)(sm + GS_A + SWZ(off)) =
                    *(const uint4*)(ag + (size_t)row * 1024 + wi);
            }
            const char* bg = (const char*)(W + (size_t)n0 * 512 + bCol);
#pragma unroll
            for (int i = 0; i < 4; i++) {
                int off = (tid + 128 * i) * 16;
                int row = off >> 7, wi = off & 127;
                *(uint4*)(sm + GS_B + SWZ(off)) =
                    *(const uint4*)(bg + (size_t)row * 1024 + wi);
            }
        }
        __syncthreads();

        u32 a[2][4][4];
#pragma unroll
        for (int mi = 0; mi < 2; mi++)
#pragma unroll
            for (int ks = 0; ks < 4; ks++)
#pragma unroll
                for (int r = 0; r < 4; r++) {
                    int row = wid * 32 + 16 * mi + g + 8 * (r & 1);
                    int kb = 4 * tig + 32 * ks + ((r >= 2) ? 16 : 0);
                    a[mi][ks][r] = *(const u32*)(sm + GS_A + SWZ(row * 128 + kb));
                }

#pragma unroll
        for (int ks = 0; ks < 4; ks++) {
            u32 b0[8], b1[8];
#pragma unroll
            for (int tt = 0; tt < 8; tt++) {
                int j = 8 * tt + g;
                int kb = 4 * tig + 32 * ks;
                b0[tt] = *(const u32*)(sm + GS_B + SWZ(j * 128 + kb));
                b1[tt] = *(const u32*)(sm + GS_B + SWZ(j * 128 + kb + 16));
            }
#pragma unroll
            for (int tt = 0; tt < 8; tt++)
#pragma unroll
                for (int mi = 0; mi < 2; mi++)
                    MMA16816(o[mi][tt], a[mi][ks], b0[tt], b1[tt]);
        }
    }

    // ---- epilogue ----
    if (MODE == 0) {
#pragma unroll
        for (int mi = 0; mi < 2; mi++)
#pragma unroll
            for (int tt = 0; tt < 8; tt++) {
                int rA = m0 + wid * 32 + 16 * mi + g;
                int cA = n0 + 8 * tt + 2 * tig;
                float2 bi = *(const float2*)(bias + cA);
                *(float2*)(out + (size_t)rA * 256 + cA) =
                    make_float2(o[mi][tt][0] + bi.x, o[mi][tt][1] + bi.y);
                *(float2*)(out + (size_t)(rA + 8) * 256 + cA) =
                    make_float2(o[mi][tt][2] + bi.x, o[mi][tt][3] + bi.y);
            }
    } else {
#pragma unroll
        for (int mi = 0; mi < 2; mi++)
#pragma unroll
            for (int tt = 0; tt < 8; tt++) {
                int cA = n0 + 8 * tt + 2 * tig;        // even
                int h = cA >> 5, d = cA & 31;
#pragma unroll
                for (int half = 0; half < 2; half++) {
                    int row = m0 + wid * 32 + 16 * mi + g + 8 * half;
                    int b_ = row >> 11, n = row & (NN - 1);
                    int bh = b_ * HH + h;
                    float v0 = o[mi][tt][2 * half] * scale;
                    float v1 = o[mi][tt][2 * half + 1] * scale;
                    u32 hp = bf16x2_of(v1, v0);
                    float r0 = __uint_as_float(hp << 16);
                    float r1 = __uint_as_float(hp & 0xffff0000u);
                    u32 lp = bf16x2_of(v1 - r1, v0 - r0);
                    if (z < 2) {
                        __nv_bfloat16* dst = (z == 0 ? g_Qb : g_Kb) + ((size_t)bh * NN + n) * 64;
                        *(u32*)(dst + d) = hp;
                        *(u32*)(dst + 32 + d) = lp;
                    } else {
                        __nv_bfloat16 h0 = __float2bfloat16(v0);
                        __nv_bfloat16 h1 = __float2bfloat16(v1);
                        __nv_bfloat16 l0 = __float2bfloat16(v0 - __bfloat162float(h0));
                        __nv_bfloat16 l1 = __float2bfloat16(v1 - __bfloat162float(h1));
                        __nv_bfloat16* vb = g_Vtb + (size_t)bh * 64 * NN + n;
                        vb[(size_t)d * NN] = h0;
                        vb[(size_t)(d + 1) * NN] = h1;
                        vb[(size_t)(d + 32) * NN] = l0;
                        vb[(size_t)(d + 33) * NN] = l1;
                    }
                }
            }
    }
}

// ---------------- HMMA flash attention ---------------------------------------
// grid (16 q-tiles, 16 bh), 128 threads = 4 warps. Warp w owns q rows [32w,32w+32).
#define SM_KB 0
#define SM_VB 8192
#define SM_MB 16384
#define SM_TOT 17408

__global__ __launch_bounds__(128) void attn_kernel() {
    __shared__ __align__(16) char sm[SM_TOT];
    const int tid = threadIdx.x;
    const int wid = tid >> 5, lane = tid & 31;
    const int g = lane >> 2, tig = lane & 3;
    const int bh = blockIdx.y, b = bh >> 3;
    const int n0 = blockIdx.x * 128;

    u32 aQ[2][4][4];
    {
        const char* qg = (const char*)g_Qb + ((size_t)(bh * NN + n0 + wid * 32)) * 128;
#pragma unroll
        for (int mi = 0; mi < 2; mi++)
#pragma unroll
            for (int ks = 0; ks < 4; ks++)
#pragma unroll
                for (int r = 0; r < 4; r++) {
                    int row = 16 * mi + g + 8 * (r & 1);
                    int kb = 4 * tig + 32 * ks + ((r >= 2) ? 16 : 0);
                    aQ[mi][ks][r] = *(const u32*)(qg + row * 128 + kb);
                }
    }

    float o[2][4][4];
#pragma unroll
    for (int mi = 0; mi < 2; mi++)
#pragma unroll
        for (int tn = 0; tn < 4; tn++)
#pragma unroll
            for (int c = 0; c < 4; c++) o[mi][tn][c] = 0.f;
    float lsum[2][2] = {{0.f, 0.f}, {0.f, 0.f}};

    for (int t = 0; t < NTILES; t++) {
        __syncthreads();
        {
            const char* kg = (const char*)g_Kb + ((size_t)(bh * NN + t * 64)) * 128;
#pragma unroll
            for (int i = 0; i < 4; i++) {
                int off = (tid + 128 * i) * 16;
                *(uint4*)(sm + SM_KB + SWZ(off)) = *(const uint4*)(kg + off);
            }
        }
        {
            const char* vg = (const char*)g_Vtb + (size_t)bh * 64 * (NN * 2) + t * 128;
#pragma unroll
            for (int i = 0; i < 4; i++) {
                int cc = tid + 128 * i;
                int d = cc >> 3, u = cc & 7;
                *(uint4*)(sm + SM_VB + SWZ(cc * 16)) =
                    *(const uint4*)(vg + (size_t)d * (NN * 2) + u * 16);
            }
        }
        *(uint2*)(sm + SM_MB + tid * 8) =
            *(const uint2*)(g_bits + ((size_t)(b * NN + n0 + tid)) * NWORDS + t * 2);
        __syncthreads();

        float cf[2][8][4];
#pragma unroll
        for (int mi = 0; mi < 2; mi++)
#pragma unroll
            for (int tt = 0; tt < 8; tt++)
#pragma unroll
                for (int c = 0; c < 4; c++) cf[mi][tt][c] = 0.f;

#pragma unroll
        for (int ks = 0; ks < 4; ks++) {
            u32 b0[8], b1[8];
#pragma unroll
            for (int tt = 0; tt < 8; tt++) {
                int j = 8 * tt + g;
                int kb = 4 * tig + 32 * ks;
                b0[tt] = *(const u32*)(sm + SM_KB + SWZ(j * 128 + kb));
                b1[tt] = *(const u32*)(sm + SM_KB + SWZ(j * 128 + kb + 16));
            }
#pragma unroll
            for (int tt = 0; tt < 8; tt++)
#pragma unroll
                for (int mi = 0; mi < 2; mi++) {
                    if (ks < 2) {
                        MMA16816(cf[mi][tt], aQ[mi][ks], b0[tt], b1[tt]);
                        MMA16816(cf[mi][tt], aQ[mi][ks + 2], b0[tt], b1[tt]);
                    } else {
                        MMA16816(cf[mi][tt], aQ[mi][ks - 2], b0[tt], b1[tt]);
                    }
                }
        }

#pragma unroll
        for (int mi = 0; mi < 2; mi++) {
            ull mA = *(const ull*)(sm + SM_MB + (wid * 32 + 16 * mi + g) * 8);
            ull mB = *(const ull*)(sm + SM_MB + (wid * 32 + 16 * mi + g + 8) * 8);
#pragma unroll
            for (int tt = 0; tt < 8; tt++) {
                int j0 = 8 * tt + 2 * tig;
                float p0 = ((mA >> j0) & 1ull)       ? __expf(cf[mi][tt][0]) : 0.f;
                float p1 = ((mA >> (j0 + 1)) & 1ull) ? __expf(cf[mi][tt][1]) : 0.f;
                float p2 = ((mB >> j0) & 1ull)       ? __expf(cf[mi][tt][2]) : 0.f;
                float p3 = ((mB >> (j0 + 1)) & 1ull) ? __expf(cf[mi][tt][3]) : 0.f;
                lsum[mi][0] += p0 + p1;
                lsum[mi][1] += p2 + p3;
                cf[mi][tt][0] = p0; cf[mi][tt][1] = p1;
                cf[mi][tt][2] = p2; cf[mi][tt][3] = p3;
            }
        }

#pragma unroll
        for (int s = 0; s < 4; s++) {
            u32 vh0[4], vh1[4], vl0[4], vl1[4];
#pragma unroll
            for (int tn = 0; tn < 4; tn++) {
                int d = 8 * tn + g;
                int jb = 4 * tig + 32 * s;
                vh0[tn] = *(const u32*)(sm + SM_VB + SWZ(d * 128 + jb));
                vh1[tn] = *(const u32*)(sm + SM_VB + SWZ(d * 128 + jb + 16));
                vl0[tn] = *(const u32*)(sm + SM_VB + SWZ((d + 32) * 128 + jb));
                vl1[tn] = *(const u32*)(sm + SM_VB + SWZ((d + 32) * 128 + jb + 16));
            }
#pragma unroll
            for (int mi = 0; mi < 2; mi++) {
                u32 Ah[4], Al[4];
#pragma unroll
                for (int half = 0; half < 2; half++) {
                    const float* c4 = cf[mi][2 * s + half];
                    u32 h01 = bf16x2_of(c4[1], c4[0]);
                    u32 h23 = bf16x2_of(c4[3], c4[2]);
                    Ah[2 * half]     = h01;
                    Ah[2 * half + 1] = h23;
                    float r0 = __uint_as_float(h01 << 16);
                    float r1 = __uint_as_float(h01 & 0xffff0000u);
                    float r2 = __uint_as_float(h23 << 16);
                    float r3 = __uint_as_float(h23 & 0xffff0000u);
                    Al[2 * half]     = bf16x2_of(c4[1] - r1, c4[0] - r0);
                    Al[2 * half + 1] = bf16x2_of(c4[3] - r3, c4[2] - r2);
                }
#pragma unroll
                for (int tn = 0; tn < 4; tn++) {
                    MMA16816(o[mi][tn], Ah, vh0[tn], vh1[tn]);
                    MMA16816(o[mi][tn], Ah, vl0[tn], vl1[tn]);
                    MMA16816(o[mi][tn], Al, vh0[tn], vh1[tn]);
                }
            }
        }
    }

#pragma unroll
    for (int mi = 0; mi < 2; mi++)
#pragma unroll
        for (int r = 0; r < 2; r++) {
            float v = lsum[mi][r];
            v += __shfl_xor_sync(0xffffffffu, v, 1);
            v += __shfl_xor_sync(0xffffffffu, v, 2);
            lsum[mi][r] = v;
        }

    // ---- normalize + write split-bf16 concat-head layout (for out proj) ----
    const int hcol = (bh & 7) * 32;
#pragma unroll
    for (int mi = 0; mi < 2; mi++) {
        int rA = n0 + wid * 32 + 16 * mi + g;
        float invA = 1.f / lsum[mi][0];
        float invB = 1.f / lsum[mi][1];
        __nv_bfloat16* baseA = g_attnb + ((size_t)b * NN + rA) * 512 + hcol;
        __nv_bfloat16* baseB = baseA + 8 * 512;
#pragma unroll
        for (int tn = 0; tn < 4; tn++) {
            int dl = 8 * tn + 2 * tig;
            float a0 = o[mi][tn][0] * invA, a1 = o[mi][tn][1] * invA;
            u32 hp = bf16x2_of(a1, a0);
            float r0 = __uint_as_float(hp << 16), r1 = __uint_as_float(hp & 0xffff0000u);
            *(u32*)(baseA + dl) = hp;
            *(u32*)(baseA + 256 + dl) = bf16x2_of(a1 - r1, a0 - r0);
            float b0_ = o[mi][tn][2] * invB, b1_ = o[mi][tn][3] * invB;
            u32 hq = bf16x2_of(b1_, b0_);
            float s0 = __uint_as_float(hq << 16), s1 = __uint_as_float(hq & 0xffff0000u);
            *(u32*)(baseB + dl) = hq;
            *(u32*)(baseB + 256 + dl) = bf16x2_of(b1_ - s1, b0_ - s0);
        }
    }
}

// ---------------- launcher ---------------------------------------------------
extern "C" void kernel_launch(void* const* d_in, const int* in_sizes, int n_in,
                              void* d_out, int out_size) {
    const float* x   = (const float*)d_in[0];
    const float* adj = (const float*)d_in[1];
    const float* Wq  = (const float*)d_in[2];
    const float* Wk  = (const float*)d_in[3];
    const float* Wv  = (const float*)d_in[4];
    const float* Wo  = (const float*)d_in[5];
    const float* bo  = (const float*)d_in[6];
    float* out = (float*)d_out;
    (void)in_sizes; (void)n_in; (void)out_size;

    void *pXb, *pAb;
    cudaGetSymbolAddress(&pXb, g_xb);
    cudaGetSymbolAddress(&pAb, g_attnb);

    adjbits_kernel<<<BB * NN * NWORDS / 256, 256>>>(adj);
    split_x<<<4096 * 64 / 256, 256>>>(x);
    split_w<<<4 * 256 * 64 / 256, 256>>>(Wq, Wk, Wv, Wo);
    hgemm<1><<<dim3(32, 4, 3), 128>>>((const __nv_bfloat16*)pXb, nullptr, nullptr);
    attn_kernel<<<dim3(NN / 128, BH), 128>>>();
    hgemm<0><<<dim3(32, 4), 128>>>((const __nv_bfloat16*)pAb, bo, out);
}

// round 12
// speedup vs baseline: 2.5768x; 1.1033x over previous
#include <cuda_runtime.h>
#include <cuda_bf16.h>
#include <cstdint>

#define BB 2
#define NN 2048
#define DIN 256
#define HH 8
#define DH 32
#define BH (BB*HH)            // 16
#define NWORDS (NN/32)        // 64
#define SCALEF 0.17677669529663688f   // 1/sqrt(32)
#define NTILES (NN/64)        // 32

typedef unsigned long long ull;
typedef uint32_t u32;

// ---------------- scratch ----------------------------------------------------
__device__ unsigned      g_bits[BB*NN*NWORDS];
__device__ __nv_bfloat16 g_Qb[BH*NN*64];    // [bh][n][hi32|lo32], prescaled
__device__ __nv_bfloat16 g_Kb[BH*NN*64];    // [bh][n][hi32|lo32]
__device__ __nv_bfloat16 g_Vtb[BH*64*NN];   // [bh][d<32 Vh^T | d>=32 Vl^T][n]
__device__ __nv_bfloat16 g_xb[4096*512];    // [row][hi256|lo256]
__device__ __nv_bfloat16 g_Wb[4*256*512];   // [w][n][hi256|lo256]  w: q,k,v,o
__device__ __nv_bfloat16 g_attnb[4096*512]; // [row][hi256|lo256]

#define SWZ(o) ((o) ^ (((o) >> 3) & 0x70))

// mma.sync m16n8k16 bf16 -> f32 accumulate (portable, sm_80+ PTX)
#define MMA16816(d, a, B0, B1) asm volatile( \
    "mma.sync.aligned.m16n8k16.row.col.f32.bf16.bf16.f32 " \
    "{%0,%1,%2,%3},{%4,%5,%6,%7},{%8,%9},{%0,%1,%2,%3};" \
    : "+f"((d)[0]), "+f"((d)[1]), "+f"((d)[2]), "+f"((d)[3]) \
    : "r"((a)[0]), "r"((a)[1]), "r"((a)[2]), "r"((a)[3]), "r"(B0), "r"(B1))

__device__ __forceinline__ u32 bf16x2_of(float hi, float lo) {
    u32 r; asm("cvt.rn.bf16x2.f32 %0, %1, %2;" : "=r"(r) : "f"(hi), "f"(lo));
    return r;   // upper half = hi arg, lower half = lo arg
}

__device__ __forceinline__ u32 smem_to_u32(const void* p) {
    u32 a;
    asm("{ .reg .u64 t; cvta.to.shared.u64 t, %1; cvt.u32.u64 %0, t; }" : "=r"(a) : "l"(p));
    return a;
}
#define CP16(dst_u32, src_ptr) asm volatile( \
    "cp.async.cg.shared.global [%0], [%1], 16;" :: "r"(dst_u32), "l"(src_ptr))
#define CP8(dst_u32, src_ptr) asm volatile( \
    "cp.async.ca.shared.global [%0], [%1], 8;" :: "r"(dst_u32), "l"(src_ptr))
#define CP_COMMIT() asm volatile("cp.async.commit_group;" ::: "memory")
#define CP_WAIT0()  asm volatile("cp.async.wait_group 0;" ::: "memory")

// ---------------- adjacency -> bitmask ---------------------------------------
__global__ __launch_bounds__(256) void adjbits_kernel(const float* __restrict__ adj) {
    int w = blockIdx.x * 256 + threadIdx.x;
    const float4* a = (const float4*)(adj + (size_t)w * 32);
    unsigned m = 0;
#pragma unroll
    for (int t = 0; t < 8; t++) {
        float4 v = a[t];
        m |= (v.x != 0.f ? 1u : 0u) << (4 * t + 0);
        m |= (v.y != 0.f ? 1u : 0u) << (4 * t + 1);
        m |= (v.z != 0.f ? 1u : 0u) << (4 * t + 2);
        m |= (v.w != 0.f ? 1u : 0u) << (4 * t + 3);
    }
    g_bits[w] = m;
}

// ---------------- split fp32 -> bf16 hi/lo ------------------------------------
__device__ __forceinline__ void split4(float4 v, u32& hA, u32& hB, u32& lA, u32& lB) {
    hA = bf16x2_of(v.y, v.x);
    hB = bf16x2_of(v.w, v.z);
    float r0 = __uint_as_float(hA << 16), r1 = __uint_as_float(hA & 0xffff0000u);
    float r2 = __uint_as_float(hB << 16), r3 = __uint_as_float(hB & 0xffff0000u);
    lA = bf16x2_of(v.y - r1, v.x - r0);
    lB = bf16x2_of(v.w - r3, v.z - r2);
}

__global__ __launch_bounds__(256) void split_x(const float* __restrict__ src) {
    int idx = blockIdx.x * 256 + threadIdx.x;      // quads over 4096*64
    float4 v = ((const float4*)src)[idx];
    int row = idx >> 6, c4 = (idx & 63) * 4;
    u32 hA, hB, lA, lB; split4(v, hA, hB, lA, lB);
    *(uint2*)(g_xb + (size_t)row * 512 + c4)       = make_uint2(hA, hB);
    *(uint2*)(g_xb + (size_t)row * 512 + 256 + c4) = make_uint2(lA, lB);
}

__global__ __launch_bounds__(256) void split_w(const float* __restrict__ Wq,
                                               const float* __restrict__ Wk,
                                               const float* __restrict__ Wv,
                                               const float* __restrict__ Wo) {
    int idx = blockIdx.x * 256 + threadIdx.x;      // quads over 4*256*64
    int w = idx >> 14;
    const float* src = (w == 0) ? Wq : (w == 1) ? Wk : (w == 2) ? Wv : Wo;
    int li = idx & 16383;
    float4 v = ((const float4*)src)[li];
    int row = li >> 6, c4 = (li & 63) * 4;
    u32 hA, hB, lA, lB; split4(v, hA, hB, lA, lB);
    __nv_bfloat16* d = g_Wb + ((size_t)w * 256 + row) * 512;
    *(uint2*)(d + c4)       = make_uint2(hA, hB);
    *(uint2*)(d + 256 + c4) = make_uint2(lA, lB);
}

// ---------------- HMMA GEMM: C(4096x256) = A(4096x256) @ W^T -----------------
// A, W split bf16 (hi|lo, 512 wide). K=768 in 12 chunks of 64:
//   p0: Ah.Wh  p1: Al.Wh  p2: Ah.Wl   (drop Al.Wl ~ 2^-16)
// cp.async double-buffered pipeline; tile 128m x 64n, 4 warps.
#define GS_A 0
#define GS_B 16384
#define GS_TILE 24576

template <int MODE>
__global__ __launch_bounds__(128) void hgemm(const __nv_bfloat16* __restrict__ A,
                                             const float* __restrict__ bias,
                                             float* __restrict__ out) {
    __shared__ __align__(1024) char sm[2 * GS_TILE];
    const u32 smb = smem_to_u32(sm);
    const int tid = threadIdx.x;
    const int wid = tid >> 5, lane = tid & 31;
    const int g = lane >> 2, tig = lane & 3;
    const int m0 = blockIdx.x * 128;
    const int n0 = blockIdx.y * 64;
    const int z = (MODE == 1) ? blockIdx.z : 3;
    const __nv_bfloat16* W = g_Wb + (size_t)z * 256 * 512;
    const float scale = (MODE == 1 && z == 0) ? SCALEF : 1.0f;

    auto stage = [&](int c) {
        const int p = c >> 2, k0 = (c & 3) * 64;
        const int aCol = ((p == 1) ? 256 : 0) + k0;
        const int bCol = ((p == 2) ? 256 : 0) + k0;
        const u32 dst = smb + ((c & 1) ? GS_TILE : 0);
        const char* ag = (const char*)(A + (size_t)m0 * 512 + aCol);
#pragma unroll
        for (int i = 0; i < 8; i++) {
            int off = (tid + 128 * i) * 16;
            int row = off >> 7, wi = off & 127;
            CP16(dst + GS_A + SWZ(off), ag + (size_t)row * 1024 + wi);
        }
        const char* bg = (const char*)(W + (size_t)n0 * 512 + bCol);
#pragma unroll
        for (int i = 0; i < 4; i++) {
            int off = (tid + 128 * i) * 16;
            int row = off >> 7, wi = off & 127;
            CP16(dst + GS_B + SWZ(off), bg + (size_t)row * 1024 + wi);
        }
        CP_COMMIT();
    };

    float o[2][8][4];
#pragma unroll
    for (int mi = 0; mi < 2; mi++)
#pragma unroll
        for (int tt = 0; tt < 8; tt++)
#pragma unroll
            for (int c = 0; c < 4; c++) o[mi][tt][c] = 0.f;

    stage(0);
#pragma unroll 1
    for (int c = 0; c < 12; c++) {
        CP_WAIT0();
        __syncthreads();
        if (c + 1 < 12) stage(c + 1);
        const char* sp = sm + ((c & 1) ? GS_TILE : 0);

        u32 a[2][4][4];
#pragma unroll
        for (int mi = 0; mi < 2; mi++)
#pragma unroll
            for (int ks = 0; ks < 4; ks++)
#pragma unroll
                for (int r = 0; r < 4; r++) {
                    int row = wid * 32 + 16 * mi + g + 8 * (r & 1);
                    int kb = 4 * tig + 32 * ks + ((r >= 2) ? 16 : 0);
                    a[mi][ks][r] = *(const u32*)(sp + GS_A + SWZ(row * 128 + kb));
                }

#pragma unroll
        for (int ks = 0; ks < 4; ks++) {
            u32 b0[8], b1[8];
#pragma unroll
            for (int tt = 0; tt < 8; tt++) {
                int j = 8 * tt + g;
                int kb = 4 * tig + 32 * ks;
                b0[tt] = *(const u32*)(sp + GS_B + SWZ(j * 128 + kb));
                b1[tt] = *(const u32*)(sp + GS_B + SWZ(j * 128 + kb + 16));
            }
#pragma unroll
            for (int tt = 0; tt < 8; tt++)
#pragma unroll
                for (int mi = 0; mi < 2; mi++)
                    MMA16816(o[mi][tt], a[mi][ks], b0[tt], b1[tt]);
        }
        __syncthreads();
    }

    // ---- epilogue ----
    if (MODE == 0) {
#pragma unroll
        for (int mi = 0; mi < 2; mi++)
#pragma unroll
            for (int tt = 0; tt < 8; tt++) {
                int rA = m0 + wid * 32 + 16 * mi + g;
                int cA = n0 + 8 * tt + 2 * tig;
                float2 bi = *(const float2*)(bias + cA);
                *(float2*)(out + (size_t)rA * 256 + cA) =
                    make_float2(o[mi][tt][0] + bi.x, o[mi][tt][1] + bi.y);
                *(float2*)(out + (size_t)(rA + 8) * 256 + cA) =
                    make_float2(o[mi][tt][2] + bi.x, o[mi][tt][3] + bi.y);
            }
    } else {
#pragma unroll
        for (int mi = 0; mi < 2; mi++)
#pragma unroll
            for (int tt = 0; tt < 8; tt++) {
                int cA = n0 + 8 * tt + 2 * tig;        // even
                int h = cA >> 5, d = cA & 31;
#pragma unroll
                for (int half = 0; half < 2; half++) {
                    int row = m0 + wid * 32 + 16 * mi + g + 8 * half;
                    int b_ = row >> 11, n = row & (NN - 1);
                    int bh = b_ * HH + h;
                    float v0 = o[mi][tt][2 * half] * scale;
                    float v1 = o[mi][tt][2 * half + 1] * scale;
                    u32 hp = bf16x2_of(v1, v0);
                    float r0 = __uint_as_float(hp << 16);
                    float r1 = __uint_as_float(hp & 0xffff0000u);
                    u32 lp = bf16x2_of(v1 - r1, v0 - r0);
                    if (z < 2) {
                        __nv_bfloat16* dst = (z == 0 ? g_Qb : g_Kb) + ((size_t)bh * NN + n) * 64;
                        *(u32*)(dst + d) = hp;
                        *(u32*)(dst + 32 + d) = lp;
                    } else {
                        __nv_bfloat16 h0 = __float2bfloat16(v0);
                        __nv_bfloat16 h1 = __float2bfloat16(v1);
                        __nv_bfloat16 l0 = __float2bfloat16(v0 - __bfloat162float(h0));
                        __nv_bfloat16 l1 = __float2bfloat16(v1 - __bfloat162float(h1));
                        __nv_bfloat16* vb = g_Vtb + (size_t)bh * 64 * NN + n;
                        vb[(size_t)d * NN] = h0;
                        vb[(size_t)(d + 1) * NN] = h1;
                        vb[(size_t)(d + 32) * NN] = l0;
                        vb[(size_t)(d + 33) * NN] = l1;
                    }
                }
            }
    }
}

// ---------------- HMMA flash attention (cp.async double-buffered) -------------
// grid (16 q-tiles, 16 bh), 128 threads = 4 warps. Warp w owns q rows [32w,32w+32).
#define SM_KB 0
#define SM_VB 8192
#define SM_MB 16384
#define SM_TILE 17408

__global__ __launch_bounds__(128) void attn_kernel() {
    __shared__ __align__(1024) char sm[2 * SM_TILE];
    const u32 smb = smem_to_u32(sm);
    const int tid = threadIdx.x;
    const int wid = tid >> 5, lane = tid & 31;
    const int g = lane >> 2, tig = lane & 3;
    const int bh = blockIdx.y, b = bh >> 3;
    const int n0 = blockIdx.x * 128;

    auto stage = [&](int t) {
        const u32 dst = smb + ((t & 1) ? SM_TILE : 0);
        const char* kg = (const char*)g_Kb + ((size_t)(bh * NN + t * 64)) * 128;
#pragma unroll
        for (int i = 0; i < 4; i++) {
            int off = (tid + 128 * i) * 16;
            CP16(dst + SM_KB + SWZ(off), kg + off);
        }
        const char* vg = (const char*)g_Vtb + (size_t)bh * 64 * (NN * 2) + t * 128;
#pragma unroll
        for (int i = 0; i < 4; i++) {
            int cc = tid + 128 * i;
            int d = cc >> 3, u = cc & 7;
            CP16(dst + SM_VB + SWZ(cc * 16), vg + (size_t)d * (NN * 2) + u * 16);
        }
        CP8(dst + SM_MB + tid * 8,
            (const char*)(g_bits + ((size_t)(b * NN + n0 + tid)) * NWORDS + t * 2));
        CP_COMMIT();
    };

    u32 aQ[2][4][4];
    {
        const char* qg = (const char*)g_Qb + ((size_t)(bh * NN + n0 + wid * 32)) * 128;
#pragma unroll
        for (int mi = 0; mi < 2; mi++)
#pragma unroll
            for (int ks = 0; ks < 4; ks++)
#pragma unroll
                for (int r = 0; r < 4; r++) {
                    int row = 16 * mi + g + 8 * (r & 1);
                    int kb = 4 * tig + 32 * ks + ((r >= 2) ? 16 : 0);
                    aQ[mi][ks][r] = *(const u32*)(qg + row * 128 + kb);
                }
    }

    float o[2][4][4];
#pragma unroll
    for (int mi = 0; mi < 2; mi++)
#pragma unroll
        for (int tn = 0; tn < 4; tn++)
#pragma unroll
            for (int c = 0; c < 4; c++) o[mi][tn][c] = 0.f;
    float lsum[2][2] = {{0.f, 0.f}, {0.f, 0.f}};

    stage(0);
#pragma unroll 1
    for (int t = 0; t < NTILES; t++) {
        CP_WAIT0();
        __syncthreads();
        if (t + 1 < NTILES) stage(t + 1);
        const char* sp = sm + ((t & 1) ? SM_TILE : 0);

        float cf[2][8][4];
#pragma unroll
        for (int mi = 0; mi < 2; mi++)
#pragma unroll
            for (int tt = 0; tt < 8; tt++)
#pragma unroll
                for (int c = 0; c < 4; c++) cf[mi][tt][c] = 0.f;

#pragma unroll
        for (int ks = 0; ks < 4; ks++) {
            u32 b0[8], b1[8];
#pragma unroll
            for (int tt = 0; tt < 8; tt++) {
                int j = 8 * tt + g;
                int kb = 4 * tig + 32 * ks;
                b0[tt] = *(const u32*)(sp + SM_KB + SWZ(j * 128 + kb));
                b1[tt] = *(const u32*)(sp + SM_KB + SWZ(j * 128 + kb + 16));
            }
#pragma unroll
            for (int tt = 0; tt < 8; tt++)
#pragma unroll
                for (int mi = 0; mi < 2; mi++) {
                    if (ks < 2) {
                        MMA16816(cf[mi][tt], aQ[mi][ks], b0[tt], b1[tt]);
                        MMA16816(cf[mi][tt], aQ[mi][ks + 2], b0[tt], b1[tt]);
                    } else {
                        MMA16816(cf[mi][tt], aQ[mi][ks - 2], b0[tt], b1[tt]);
                    }
                }
        }

#pragma unroll
        for (int mi = 0; mi < 2; mi++) {
            ull mA = *(const ull*)(sp + SM_MB + (wid * 32 + 16 * mi + g) * 8);
            ull mB = *(const ull*)(sp + SM_MB + (wid * 32 + 16 * mi + g + 8) * 8);
#pragma unroll
            for (int tt = 0; tt < 8; tt++) {
                int j0 = 8 * tt + 2 * tig;
                float p0 = ((mA >> j0) & 1ull)       ? __expf(cf[mi][tt][0]) : 0.f;
                float p1 = ((mA >> (j0 + 1)) & 1ull) ? __expf(cf[mi][tt][1]) : 0.f;
                float p2 = ((mB >> j0) & 1ull)       ? __expf(cf[mi][tt][2]) : 0.f;
                float p3 = ((mB >> (j0 + 1)) & 1ull) ? __expf(cf[mi][tt][3]) : 0.f;
                lsum[mi][0] += p0 + p1;
                lsum[mi][1] += p2 + p3;
                cf[mi][tt][0] = p0; cf[mi][tt][1] = p1;
                cf[mi][tt][2] = p2; cf[mi][tt][3] = p3;
            }
        }

#pragma unroll
        for (int s = 0; s < 4; s++) {
            u32 vh0[4], vh1[4], vl0[4], vl1[4];
#pragma unroll
            for (int tn = 0; tn < 4; tn++) {
                int d = 8 * tn + g;
                int jb = 4 * tig + 32 * s;
                vh0[tn] = *(const u32*)(sp + SM_VB + SWZ(d * 128 + jb));
                vh1[tn] = *(const u32*)(sp + SM_VB + SWZ(d * 128 + jb + 16));
                vl0[tn] = *(const u32*)(sp + SM_VB + SWZ((d + 32) * 128 + jb));
                vl1[tn] = *(const u32*)(sp + SM_VB + SWZ((d + 32) * 128 + jb + 16));
            }
#pragma unroll
            for (int mi = 0; mi < 2; mi++) {
                u32 Ah[4], Al[4];
#pragma unroll
                for (int half = 0; half < 2; half++) {
                    const float* c4 = cf[mi][2 * s + half];
                    u32 h01 = bf16x2_of(c4[1], c4[0]);
                    u32 h23 = bf16x2_of(c4[3], c4[2]);
                    Ah[2 * half]     = h01;
                    Ah[2 * half + 1] = h23;
                    float r0 = __uint_as_float(h01 << 16);
                    float r1 = __uint_as_float(h01 & 0xffff0000u);
                    float r2 = __uint_as_float(h23 << 16);
                    float r3 = __uint_as_float(h23 & 0xffff0000u);
                    Al[2 * half]     = bf16x2_of(c4[1] - r1, c4[0] - r0);
                    Al[2 * half + 1] = bf16x2_of(c4[3] - r3, c4[2] - r2);
                }
#pragma unroll
                for (int tn = 0; tn < 4; tn++) {
                    MMA16816(o[mi][tn], Ah, vh0[tn], vh1[tn]);
                    MMA16816(o[mi][tn], Ah, vl0[tn], vl1[tn]);
                    MMA16816(o[mi][tn], Al, vh0[tn], vh1[tn]);
                }
            }
        }
        __syncthreads();
    }

#pragma unroll
    for (int mi = 0; mi < 2; mi++)
#pragma unroll
        for (int r = 0; r < 2; r++) {
            float v = lsum[mi][r];
            v += __shfl_xor_sync(0xffffffffu, v, 1);
            v += __shfl_xor_sync(0xffffffffu, v, 2);
            lsum[mi][r] = v;
        }

    // ---- normalize + write split-bf16 concat-head layout (for out proj) ----
    const int hcol = (bh & 7) * 32;
#pragma unroll
    for (int mi = 0; mi < 2; mi++) {
        int rA = n0 + wid * 32 + 16 * mi + g;
        float invA = 1.f / lsum[mi][0];
        float invB = 1.f / lsum[mi][1];
        __nv_bfloat16* baseA = g_attnb + ((size_t)b * NN + rA) * 512 + hcol;
        __nv_bfloat16* baseB = baseA + 8 * 512;
#pragma unroll
        for (int tn = 0; tn < 4; tn++) {
            int dl = 8 * tn + 2 * tig;
            float a0 = o[mi][tn][0] * invA, a1 = o[mi][tn][1] * invA;
            u32 hp = bf16x2_of(a1, a0);
            float r0 = __uint_as_float(hp << 16), r1 = __uint_as_float(hp & 0xffff0000u);
            *(u32*)(baseA + dl) = hp;
            *(u32*)(baseA + 256 + dl) = bf16x2_of(a1 - r1, a0 - r0);
            float b0_ = o[mi][tn][2] * invB, b1_ = o[mi][tn][3] * invB;
            u32 hq = bf16x2_of(b1_, b0_);
            float s0 = __uint_as_float(hq << 16), s1 = __uint_as_float(hq & 0xffff0000u);
            *(u32*)(baseB + dl) = hq;
            *(u32*)(baseB + 256 + dl) = bf16x2_of(b1_ - s1, b0_ - s0);
        }
    }
}

// ---------------- launcher ---------------------------------------------------
extern "C" void kernel_launch(void* const* d_in, const int* in_sizes, int n_in,
                              void* d_out, int out_size) {
    const float* x   = (const float*)d_in[0];
    const float* adj = (const float*)d_in[1];
    const float* Wq  = (const float*)d_in[2];
    const float* Wk  = (const float*)d_in[3];
    const float* Wv  = (const float*)d_in[4];
    const float* Wo  = (const float*)d_in[5];
    const float* bo  = (const float*)d_in[6];
    float* out = (float*)d_out;
    (void)in_sizes; (void)n_in; (void)out_size;

    void *pXb, *pAb;
    cudaGetSymbolAddress(&pXb, g_xb);
    cudaGetSymbolAddress(&pAb, g_attnb);

    adjbits_kernel<<<BB * NN * NWORDS / 256, 256>>>(adj);
    split_x<<<4096 * 64 / 256, 256>>>(x);
    split_w<<<4 * 256 * 64 / 256, 256>>>(Wq, Wk, Wv, Wo);
    hgemm<1><<<dim3(32, 4, 3), 128>>>((const __nv_bfloat16*)pXb, nullptr, nullptr);
    attn_kernel<<<dim3(NN / 128, BH), 128>>>();
    hgemm<0><<<dim3(32, 4), 128>>>((const __nv_bfloat16*)pAb, bo, out);
}